// round 7
// baseline (speedup 1.0000x reference)
#include <cuda_runtime.h>
#include <cuda_fp16.h>

#define BB    16
#define NN    65536
#define CC    256
#define DINN  16
#define DOUTT 16

__device__ __align__(16) __half g_s[DINN * BB * CC];      // s: [i][b][k], fp16
__device__ __align__(16) float  g_wdt[CC * DOUTT * DINN]; // w_diag: [c][o][i]
__device__ __align__(16) float  g_off[BB * CC * DOUTT];   // off: [b][c][o]

__device__ __forceinline__ float4 shfl_xor_f4(float4 v, int m) {
    v.x = __shfl_xor_sync(0xffffffffu, v.x, m);
    v.y = __shfl_xor_sync(0xffffffffu, v.y, m);
    v.z = __shfl_xor_sync(0xffffffffu, v.z, m);
    v.w = __shfl_xor_sync(0xffffffffu, v.w, m);
    return v;
}
__device__ __forceinline__ float dot4(float4 a, float4 b) {
    return a.x*b.x + a.y*b.y + a.z*b.z + a.w*b.w;
}

// ---------------------------------------------------------------------------
// kT: transpose w_diag [o][i][c] -> [c][o*16+i]
// ---------------------------------------------------------------------------
__global__ __launch_bounds__(256) void kT(const float* __restrict__ wdiag) {
    int idx = blockIdx.x * 256 + threadIdx.x;
    int c  = idx & 255;
    int oi = idx >> 8;
    g_wdt[c * 256 + oi] = wdiag[idx];
}

// ---------------------------------------------------------------------------
// kA: s[i][b][c] = sum_r x[b, pid[c*256+r], i]   (fp16 out)
// Per-thread __ldg ids (no smem/barrier for ids); q-split gather; 2-stage reduce.
// ---------------------------------------------------------------------------
__global__ __launch_bounds__(256) void kA(const float* __restrict__ x,
                                          const int* __restrict__ pid) {
    int c = blockIdx.x, b = blockIdx.y;
    __shared__ float4 red[32];
    int t = threadIdx.x;
    int q = t & 3, g = t >> 2;
    int warp = t >> 5, lane = t & 31;

    const int* pc = pid + c * 256;
    int n0 = __ldg(pc + g);
    int n1 = __ldg(pc + g + 64);
    int n2 = __ldg(pc + g + 128);
    int n3 = __ldg(pc + g + 192);

    const float* xb = x + (size_t)b * NN * DINN;
    float4 v0 = ((const float4*)(xb + (size_t)n0 * DINN))[q];
    float4 v1 = ((const float4*)(xb + (size_t)n1 * DINN))[q];
    float4 v2 = ((const float4*)(xb + (size_t)n2 * DINN))[q];
    float4 v3 = ((const float4*)(xb + (size_t)n3 * DINN))[q];

    float4 acc = make_float4(v0.x+v1.x+v2.x+v3.x, v0.y+v1.y+v2.y+v3.y,
                             v0.z+v1.z+v2.z+v3.z, v0.w+v1.w+v2.w+v3.w);
#pragma unroll
    for (int m = 4; m < 32; m <<= 1) {
        float4 o = shfl_xor_f4(acc, m);
        acc.x += o.x; acc.y += o.y; acc.z += o.z; acc.w += o.w;
    }
    if (lane < 4) red[warp * 4 + lane] = acc;
    __syncthreads();
    if (t < 32) {
        float4 v = red[t];
#pragma unroll
        for (int m = 4; m < 32; m <<= 1) {
            float4 o = shfl_xor_f4(v, m);
            v.x += o.x; v.y += o.y; v.z += o.z; v.w += o.w;
        }
        if (t < 4) {
            int i0 = 4 * t;
            g_s[((i0 + 0) * BB + b) * CC + c] = __float2half(v.x);
            g_s[((i0 + 1) * BB + b) * CC + c] = __float2half(v.y);
            g_s[((i0 + 2) * BB + b) * CC + c] = __float2half(v.z);
            g_s[((i0 + 3) * BB + b) * CC + c] = __float2half(v.w);
        }
    }
}

// ---------------------------------------------------------------------------
// kB v3: off[b][c][o] = (1/N)*sum_{i,k} w_off[o][i][c][k]*s[b][k][i]
// grid (C, 2): y = o-half. 256 thr = 8 warps; warp w -> single o = 8y+w.
// 512 blocks -> ~3.5/SM -> 28 warps/SM to hide w_off DRAM latency.
// Two i-slices staged per barrier round (16 KB smem).
// ---------------------------------------------------------------------------
__global__ __launch_bounds__(256) void kB(const float* __restrict__ woff) {
    int c    = blockIdx.x;
    int y    = blockIdx.y;
    int t    = threadIdx.x;
    int w    = t >> 5;
    int lane = t & 31;
    int o    = 8 * y + w;

    __shared__ __align__(16) __half2 sh[2 * 16 * 128];   // [slice][b][h]

    __half2 acc[16];
#pragma unroll
    for (int b = 0; b < 16; b++) acc[b] = __float2half2_rn(0.f);

    const uint4* gs4 = (const uint4*)g_s;

    for (int ii = 0; ii < 8; ii++) {
        __syncthreads();
        // copy slices 2ii, 2ii+1 : 16 KB = 1024 uint4
        for (int qq = t; qq < 1024; qq += 256)
            ((uint4*)sh)[qq] = gs4[ii * 1024 + qq];
        __syncthreads();

#pragma unroll
        for (int d = 0; d < 2; d++) {
            int i = 2 * ii + d;
            const float2* wb = (const float2*)(woff + (((size_t)o * 16 + i) * CC + c) * CC);
            const __half2* sl = sh + d * 2048;
#pragma unroll
            for (int stp = 0; stp < 4; stp++) {
                int h = stp * 32 + lane;
                float2 wf = __ldg(wb + h);
                __half2 wh = __floats2half2_rn(wf.x, wf.y);
#pragma unroll
                for (int b = 0; b < 16; b++)
                    acc[b] = __hfma2(wh, sl[b * 128 + h], acc[b]);
            }
        }
    }

    const float invN = 1.0f / (float)NN;
    float fb[16];
#pragma unroll
    for (int b = 0; b < 16; b++) {
        float f = __low2float(acc[b]) + __high2float(acc[b]);
#pragma unroll
        for (int m = 16; m > 0; m >>= 1)
            f += __shfl_xor_sync(0xffffffffu, f, m);
        fb[b] = f;
    }
    if (lane == 0) {
#pragma unroll
        for (int b = 0; b < 16; b++)
            g_off[((size_t)b * CC + c) * DOUTT + o] = fb[b] * invN;
    }
}

// ---------------------------------------------------------------------------
// kC (measured 32.3-32.6us): grid (C,B), 256 thr, sync-free prologue,
// 4 lanes/row, quarters via shfl_xor, weights in regs (q^p order), <=85 regs.
// ---------------------------------------------------------------------------
__global__ __launch_bounds__(256, 3) void kC(const float* __restrict__ x,
                                             const int* __restrict__ pid,
                                             const float* __restrict__ b1,
                                             float* __restrict__ out) {
    int c = blockIdx.x, b = blockIdx.y;
    int t = threadIdx.x;
    int q = t & 3, g = t >> 2;

    const int* pc = pid + c * 256;
    int ns[4];
    ns[0] = __ldg(pc + g);
    ns[1] = __ldg(pc + g + 64);
    ns[2] = __ldg(pc + g + 128);
    ns[3] = __ldg(pc + g + 192);

    float4 wreg[4][4];
    float  bs[4];
    const float* wc = g_wdt + c * 256;
#pragma unroll
    for (int oo = 0; oo < 4; oo++) {
        int o = 4 * q + oo;
        bs[oo] = __ldg(&g_off[((size_t)b * CC + c) * DOUTT + o]) + __ldg(b1 + o);
#pragma unroll
        for (int p = 0; p < 4; p++)
            wreg[oo][p] = *(const float4*)(wc + o * 16 + 4 * (q ^ p));
    }

    const float* xb = x + (size_t)b * NN * DINN;
    float* ob = out + (size_t)b * NN * DOUTT;

#pragma unroll
    for (int j = 0; j < 4; j++) {
        int n = ns[j];
        float4 X0 = ((const float4*)(xb + (size_t)n * DINN))[q];
        float4 X1 = shfl_xor_f4(X0, 1);
        float4 X2 = shfl_xor_f4(X0, 2);
        float4 X3 = shfl_xor_f4(X0, 3);

        float r0 = bs[0], r1 = bs[1], r2 = bs[2], r3 = bs[3];
        r0 += dot4(wreg[0][0], X0) + dot4(wreg[0][1], X1) + dot4(wreg[0][2], X2) + dot4(wreg[0][3], X3);
        r1 += dot4(wreg[1][0], X0) + dot4(wreg[1][1], X1) + dot4(wreg[1][2], X2) + dot4(wreg[1][3], X3);
        r2 += dot4(wreg[2][0], X0) + dot4(wreg[2][1], X1) + dot4(wreg[2][2], X2) + dot4(wreg[2][3], X3);
        r3 += dot4(wreg[3][0], X0) + dot4(wreg[3][1], X1) + dot4(wreg[3][2], X2) + dot4(wreg[3][3], X3);

        ((float4*)(ob + (size_t)n * DOUTT))[q] = make_float4(r0, r1, r2, r3);
    }
}

extern "C" void kernel_launch(void* const* d_in, const int* in_sizes, int n_in,
                              void* d_out, int out_size) {
    const float* x     = (const float*)d_in[0];
    const float* wdiag = (const float*)d_in[1];
    const float* woff  = (const float*)d_in[2];
    const float* b1    = (const float*)d_in[3];
    const int*   pid   = (const int*)d_in[4];
    float* out = (float*)d_out;

    kT<<<256, 256>>>(wdiag);
    kA<<<dim3(CC, BB), 256>>>(x, pid);
    kB<<<dim3(CC, 2), 256>>>(woff);
    kC<<<dim3(CC, BB), 256>>>(x, pid, b1, out);
}

// round 9
// speedup vs baseline: 1.1185x; 1.1185x over previous
#include <cuda_runtime.h>
#include <cuda_fp16.h>

#define BB    16
#define NN    65536
#define CC    256
#define DINN  16
#define DOUTT 16

__device__ __align__(16) float  g_sf[DINN * BB * CC];     // s: [i][b][k], fp32 (atomic acc)
__device__ __align__(16) float  g_wdt[CC * DOUTT * DINN]; // w_diag: [c][o][i]
__device__ __align__(16) float  g_off[BB * CC * DOUTT];   // off: [b][c][o]

__device__ __forceinline__ float4 shfl_xor_f4(float4 v, int m) {
    v.x = __shfl_xor_sync(0xffffffffu, v.x, m);
    v.y = __shfl_xor_sync(0xffffffffu, v.y, m);
    v.z = __shfl_xor_sync(0xffffffffu, v.z, m);
    v.w = __shfl_xor_sync(0xffffffffu, v.w, m);
    return v;
}
__device__ __forceinline__ float dot4(float4 a, float4 b) {
    return a.x*b.x + a.y*b.y + a.z*b.z + a.w*b.w;
}

// ---------------------------------------------------------------------------
// kT: transpose w_diag [o][i][c] -> [c][o*16+i]; zero g_sf for kA atomics
// ---------------------------------------------------------------------------
__global__ __launch_bounds__(256) void kT(const float* __restrict__ wdiag) {
    int idx = blockIdx.x * 256 + threadIdx.x;
    int c  = idx & 255;
    int oi = idx >> 8;
    g_wdt[c * 256 + oi] = wdiag[idx];
    g_sf[idx] = 0.f;                       // 65536 floats exactly
}

// ---------------------------------------------------------------------------
// kA: s[i][b][c] += sum_r x[b, pid[c*256+r], i]  — barrier-free.
// grid (C,B), 256 thr. q = t&3, g = t>>2. Warp reduces its 8 g-groups via
// 3 shfl rounds; lanes 0-3 atomicAdd 4 floats each into g_sf. No smem.
// ---------------------------------------------------------------------------
__global__ __launch_bounds__(256) void kA(const float* __restrict__ x,
                                          const int* __restrict__ pid) {
    int c = blockIdx.x, b = blockIdx.y;
    int t = threadIdx.x;
    int q = t & 3, g = t >> 2;
    int lane = t & 31;

    const int* pc = pid + c * 256;
    int n0 = __ldg(pc + g);
    int n1 = __ldg(pc + g + 64);
    int n2 = __ldg(pc + g + 128);
    int n3 = __ldg(pc + g + 192);

    const float* xb = x + (size_t)b * NN * DINN;
    float4 v0 = ((const float4*)(xb + (size_t)n0 * DINN))[q];
    float4 v1 = ((const float4*)(xb + (size_t)n1 * DINN))[q];
    float4 v2 = ((const float4*)(xb + (size_t)n2 * DINN))[q];
    float4 v3 = ((const float4*)(xb + (size_t)n3 * DINN))[q];

    float4 acc = make_float4(v0.x+v1.x+v2.x+v3.x, v0.y+v1.y+v2.y+v3.y,
                             v0.z+v1.z+v2.z+v3.z, v0.w+v1.w+v2.w+v3.w);
#pragma unroll
    for (int m = 4; m < 32; m <<= 1) {
        float4 o = shfl_xor_f4(acc, m);
        acc.x += o.x; acc.y += o.y; acc.z += o.z; acc.w += o.w;
    }
    if (lane < 4) {                        // lane == q; acc = 32-row partial
        int i0 = 4 * lane;
        atomicAdd(&g_sf[((i0 + 0) * BB + b) * CC + c], acc.x);
        atomicAdd(&g_sf[((i0 + 1) * BB + b) * CC + c], acc.y);
        atomicAdd(&g_sf[((i0 + 2) * BB + b) * CC + c], acc.z);
        atomicAdd(&g_sf[((i0 + 3) * BB + b) * CC + c], acc.w);
    }
}

// ---------------------------------------------------------------------------
// kB: off[b][c][o] = (1/N)*sum_{i,k} w_off[o][i][c][k]*s[b][k][i]
// grid C, 256 thr (8 warps); warp w -> o = {2w, 2w+1}; i-slice staged in smem
// with on-the-fly fp32 -> half2 conversion. R2-proven HFMA2 MAC loop.
// ---------------------------------------------------------------------------
__global__ __launch_bounds__(256) void kB(const float* __restrict__ woff) {
    int c    = blockIdx.x;
    int t    = threadIdx.x;
    int w    = t >> 5;
    int lane = t & 31;
    int o0 = 2 * w, o1 = o0 + 1;

    __shared__ __align__(16) __half2 sh[16 * 128];   // [b][h], h = k/2

    __half2 acc0[16], acc1[16];
#pragma unroll
    for (int b = 0; b < 16; b++) {
        acc0[b] = __float2half2_rn(0.f);
        acc1[b] = __float2half2_rn(0.f);
    }

    const float4* gsf4 = (const float4*)g_sf;        // slice i = 1024 float4

    for (int i = 0; i < 16; i++) {
        __syncthreads();
        for (int f = t; f < 1024; f += 256) {
            float4 v = gsf4[i * 1024 + f];
            int bq = f >> 6;               // b
            int k0 = (f & 63) << 2;        // k0 = 0,4,...,252
            __half2 h0 = __floats2half2_rn(v.x, v.y);
            __half2 h1 = __floats2half2_rn(v.z, v.w);
            *(uint2*)&sh[bq * 128 + (k0 >> 1)] =
                make_uint2(*(unsigned*)&h0, *(unsigned*)&h1);
        }
        __syncthreads();

        const float2* wb0 = (const float2*)(woff + (((size_t)o0 * 16 + i) * CC + c) * CC);
        const float2* wb1 = (const float2*)(woff + (((size_t)o1 * 16 + i) * CC + c) * CC);
#pragma unroll
        for (int stp = 0; stp < 4; stp++) {
            int h = stp * 32 + lane;
            float2 wf0 = wb0[h];
            float2 wf1 = wb1[h];
            __half2 wh0 = __floats2half2_rn(wf0.x, wf0.y);
            __half2 wh1 = __floats2half2_rn(wf1.x, wf1.y);
#pragma unroll
            for (int b = 0; b < 16; b++) {
                __half2 sv = sh[b * 128 + h];
                acc0[b] = __hfma2(wh0, sv, acc0[b]);
                acc1[b] = __hfma2(wh1, sv, acc1[b]);
            }
        }
    }

    const float invN = 1.0f / (float)NN;
#pragma unroll
    for (int b = 0; b < 16; b++) {
        float f0 = __low2float(acc0[b]) + __high2float(acc0[b]);
        float f1 = __low2float(acc1[b]) + __high2float(acc1[b]);
#pragma unroll
        for (int off = 16; off > 0; off >>= 1) {
            f0 += __shfl_xor_sync(0xffffffffu, f0, off);
            f1 += __shfl_xor_sync(0xffffffffu, f1, off);
        }
        if (lane == 0) {
            g_off[((size_t)b * CC + c) * DOUTT + o0] = f0 * invN;
            g_off[((size_t)b * CC + c) * DOUTT + o1] = f1 * invN;
        }
    }
}

// ---------------------------------------------------------------------------
// kC (measured best): grid (C,B), 256 thr, sync-free prologue, 4 lanes/row,
// quarters via shfl_xor, weights in regs (q^p order), <=85 regs.
// ---------------------------------------------------------------------------
__global__ __launch_bounds__(256, 3) void kC(const float* __restrict__ x,
                                             const int* __restrict__ pid,
                                             const float* __restrict__ b1,
                                             float* __restrict__ out) {
    int c = blockIdx.x, b = blockIdx.y;
    int t = threadIdx.x;
    int q = t & 3, g = t >> 2;

    const int* pc = pid + c * 256;
    int ns[4];
    ns[0] = __ldg(pc + g);
    ns[1] = __ldg(pc + g + 64);
    ns[2] = __ldg(pc + g + 128);
    ns[3] = __ldg(pc + g + 192);

    float4 wreg[4][4];
    float  bs[4];
    const float* wc = g_wdt + c * 256;
#pragma unroll
    for (int oo = 0; oo < 4; oo++) {
        int o = 4 * q + oo;
        bs[oo] = __ldg(&g_off[((size_t)b * CC + c) * DOUTT + o]) + __ldg(b1 + o);
#pragma unroll
        for (int p = 0; p < 4; p++)
            wreg[oo][p] = *(const float4*)(wc + o * 16 + 4 * (q ^ p));
    }

    const float* xb = x + (size_t)b * NN * DINN;
    float* ob = out + (size_t)b * NN * DOUTT;

#pragma unroll
    for (int j = 0; j < 4; j++) {
        int n = ns[j];
        float4 X0 = ((const float4*)(xb + (size_t)n * DINN))[q];
        float4 X1 = shfl_xor_f4(X0, 1);
        float4 X2 = shfl_xor_f4(X0, 2);
        float4 X3 = shfl_xor_f4(X0, 3);

        float r0 = bs[0], r1 = bs[1], r2 = bs[2], r3 = bs[3];
        r0 += dot4(wreg[0][0], X0) + dot4(wreg[0][1], X1) + dot4(wreg[0][2], X2) + dot4(wreg[0][3], X3);
        r1 += dot4(wreg[1][0], X0) + dot4(wreg[1][1], X1) + dot4(wreg[1][2], X2) + dot4(wreg[1][3], X3);
        r2 += dot4(wreg[2][0], X0) + dot4(wreg[2][1], X1) + dot4(wreg[2][2], X2) + dot4(wreg[2][3], X3);
        r3 += dot4(wreg[3][0], X0) + dot4(wreg[3][1], X1) + dot4(wreg[3][2], X2) + dot4(wreg[3][3], X3);

        ((float4*)(ob + (size_t)n * DOUTT))[q] = make_float4(r0, r1, r2, r3);
    }
}

extern "C" void kernel_launch(void* const* d_in, const int* in_sizes, int n_in,
                              void* d_out, int out_size) {
    const float* x     = (const float*)d_in[0];
    const float* wdiag = (const float*)d_in[1];
    const float* woff  = (const float*)d_in[2];
    const float* b1    = (const float*)d_in[3];
    const int*   pid   = (const int*)d_in[4];
    float* out = (float*)d_out;

    kT<<<256, 256>>>(wdiag);
    kA<<<dim3(CC, BB), 256>>>(x, pid);
    kB<<<CC, 256>>>(woff);
    kC<<<dim3(CC, BB), 256>>>(x, pid, b1, out);
}

// round 10
// speedup vs baseline: 1.5084x; 1.3486x over previous
#include <cuda_runtime.h>
#include <cuda_fp16.h>

#define BB    16
#define NN    65536
#define CC    256
#define DINN  16
#define DOUTT 16

__device__ __align__(16) __half g_s[DINN * BB * CC];      // s: [i][b][k], fp16
__device__ __align__(16) float  g_wdt[CC * DOUTT * DINN]; // w_diag: [c][o][i]
__device__ __align__(16) float  g_off[BB * CC * DOUTT];   // off: [b][c][o]

__device__ __forceinline__ float4 shfl_xor_f4(float4 v, int m) {
    v.x = __shfl_xor_sync(0xffffffffu, v.x, m);
    v.y = __shfl_xor_sync(0xffffffffu, v.y, m);
    v.z = __shfl_xor_sync(0xffffffffu, v.z, m);
    v.w = __shfl_xor_sync(0xffffffffu, v.w, m);
    return v;
}
__device__ __forceinline__ float dot4(float4 a, float4 b) {
    return a.x*b.x + a.y*b.y + a.z*b.z + a.w*b.w;
}
__device__ __forceinline__ void mma16816(float& d0, float& d1, float& d2, float& d3,
                                         unsigned a0, unsigned a1, unsigned a2, unsigned a3,
                                         unsigned b0, unsigned b1) {
    asm volatile(
        "mma.sync.aligned.m16n8k16.row.col.f32.f16.f16.f32 "
        "{%0,%1,%2,%3}, {%4,%5,%6,%7}, {%8,%9}, {%0,%1,%2,%3};\n"
        : "+f"(d0), "+f"(d1), "+f"(d2), "+f"(d3)
        : "r"(a0), "r"(a1), "r"(a2), "r"(a3), "r"(b0), "r"(b1));
}

// ---------------------------------------------------------------------------
// kT: transpose w_diag [o][i][c] -> [c][o*16+i]   (R6 exact)
// ---------------------------------------------------------------------------
__global__ __launch_bounds__(256) void kT(const float* __restrict__ wdiag) {
    int idx = blockIdx.x * 256 + threadIdx.x;
    int c  = idx & 255;
    int oi = idx >> 8;
    g_wdt[c * 256 + oi] = wdiag[idx];
}

// ---------------------------------------------------------------------------
// kA: s[i][b][c] = sum_r x[b, pid[c*256+r], i]   (R6 exact)
// ---------------------------------------------------------------------------
__global__ __launch_bounds__(256) void kA(const float* __restrict__ x,
                                          const int* __restrict__ pid) {
    int c = blockIdx.x, b = blockIdx.y;
    __shared__ int ids[256];
    __shared__ float4 red[32];
    int t = threadIdx.x;
    int q = t & 3, g = t >> 2;
    int warp = t >> 5, lane = t & 31;
    ids[t] = pid[c * 256 + t];
    __syncthreads();

    const float* xb = x + (size_t)b * NN * DINN;
    float4 acc = make_float4(0.f, 0.f, 0.f, 0.f);
#pragma unroll
    for (int j = 0; j < 4; j++) {
        int n = ids[g + 64 * j];
        float4 v = ((const float4*)(xb + (size_t)n * DINN))[q];
        acc.x += v.x; acc.y += v.y; acc.z += v.z; acc.w += v.w;
    }
#pragma unroll
    for (int m = 4; m < 32; m <<= 1) {
        float4 o = shfl_xor_f4(acc, m);
        acc.x += o.x; acc.y += o.y; acc.z += o.z; acc.w += o.w;
    }
    if (lane < 4) red[warp * 4 + lane] = acc;
    __syncthreads();
    if (t < 32) {
        float4 v = red[t];
#pragma unroll
        for (int m = 4; m < 32; m <<= 1) {
            float4 o = shfl_xor_f4(v, m);
            v.x += o.x; v.y += o.y; v.z += o.z; v.w += o.w;
        }
        if (t < 4) {
            int i0 = 4 * t;
            g_s[((i0 + 0) * BB + b) * CC + c] = __float2half(v.x);
            g_s[((i0 + 1) * BB + b) * CC + c] = __float2half(v.y);
            g_s[((i0 + 2) * BB + b) * CC + c] = __float2half(v.z);
            g_s[((i0 + 3) * BB + b) * CC + c] = __float2half(v.w);
        }
    }
}

// ---------------------------------------------------------------------------
// kB (tensor-core): per c, D[16b][16o] = sum_kappa s[b][kappa] * w_off[kappa][o]
// kappa = (i,k). grid C, 256 thr = 8 warps; warp w owns k-window [32w, 32w+32).
// Per i-slice: stage s (fp16 from g_s) + w_off (fp32->fp16) in smem, then
// 2 ksteps x 2 n-halves of mma.m16n8k16 with f32 accum. w_off stream is
// register double-buffered (4x LDG.128/thread prefetched for slice i+1).
// Cross-warp reduce of 8 D-partials via smem at the end.
// ---------------------------------------------------------------------------
__global__ __launch_bounds__(256) void kB(const float* __restrict__ woff) {
    int c    = blockIdx.x;
    int t    = threadIdx.x;
    int w    = t >> 5;
    int lane = t & 31;
    int r    = lane >> 2;          // groupID
    int cp   = (lane & 3) * 2;     // threadID_in_group * 2
    int W    = w * 32;             // k-window base

    __shared__ __align__(16) __half sh_s[16 * 256];   // [b][k]   8 KB
    __shared__ __align__(16) __half sh_w[16 * 256];   // [o][k]   8 KB
    __shared__ __align__(16) float  dred[8 * 256];    // [w][b*16+o] 8 KB

    // w-staging assignment: rounds rr=0..3, F = t + 256*rr (float4 index)
    // o = F>>6, k4 = F&63 -> 4 floats at k = 4*k4
    int so[4], sk4[4];
#pragma unroll
    for (int rr = 0; rr < 4; rr++) {
        int F = t + 256 * rr;
        so[rr]  = F >> 6;
        sk4[rr] = F & 63;
    }

    float4 wbuf[4];
    uint4  sbuf0, sbuf1;
    const uint4* gs4 = (const uint4*)g_s;

    // preload slice 0
#pragma unroll
    for (int rr = 0; rr < 4; rr++)
        wbuf[rr] = __ldg((const float4*)(woff + (((size_t)so[rr] * 16 + 0) * CC + c) * CC) + sk4[rr]);
    sbuf0 = gs4[t];
    sbuf1 = gs4[256 + t];

    float d0[4] = {0.f, 0.f, 0.f, 0.f};   // n-half 0
    float d1[4] = {0.f, 0.f, 0.f, 0.f};   // n-half 1

    for (int i = 0; i < 16; i++) {
        // store staged slice i
#pragma unroll
        for (int rr = 0; rr < 4; rr++) {
            __half2 h0 = __floats2half2_rn(wbuf[rr].x, wbuf[rr].y);
            __half2 h1 = __floats2half2_rn(wbuf[rr].z, wbuf[rr].w);
            *(uint2*)&sh_w[so[rr] * 256 + sk4[rr] * 4] =
                make_uint2(*(unsigned*)&h0, *(unsigned*)&h1);
        }
        ((uint4*)sh_s)[t]       = sbuf0;
        ((uint4*)sh_s)[t + 256] = sbuf1;
        __syncthreads();

        // prefetch slice i+1
        if (i < 15) {
#pragma unroll
            for (int rr = 0; rr < 4; rr++)
                wbuf[rr] = __ldg((const float4*)(woff + (((size_t)so[rr] * 16 + (i + 1)) * CC + c) * CC) + sk4[rr]);
            sbuf0 = gs4[(i + 1) * 512 + t];
            sbuf1 = gs4[(i + 1) * 512 + 256 + t];
        }

        // compute: 2 ksteps x 2 n-halves
#pragma unroll
        for (int ks = 0; ks < 2; ks++) {
            int kb = W + ks * 16 + cp;
            unsigned a0 = *(const unsigned*)&sh_s[r * 256 + kb];
            unsigned a1 = *(const unsigned*)&sh_s[(r + 8) * 256 + kb];
            unsigned a2 = *(const unsigned*)&sh_s[r * 256 + kb + 8];
            unsigned a3 = *(const unsigned*)&sh_s[(r + 8) * 256 + kb + 8];
            unsigned b00 = *(const unsigned*)&sh_w[r * 256 + kb];
            unsigned b01 = *(const unsigned*)&sh_w[r * 256 + kb + 8];
            unsigned b10 = *(const unsigned*)&sh_w[(8 + r) * 256 + kb];
            unsigned b11 = *(const unsigned*)&sh_w[(8 + r) * 256 + kb + 8];
            mma16816(d0[0], d0[1], d0[2], d0[3], a0, a1, a2, a3, b00, b01);
            mma16816(d1[0], d1[1], d1[2], d1[3], a0, a1, a2, a3, b10, b11);
        }
        __syncthreads();
    }

    // write warp partials: D[b][o], b = r / r+8, o = nh*8 + cp..cp+1
    *(float2*)&dred[w * 256 + r * 16 + cp]            = make_float2(d0[0], d0[1]);
    *(float2*)&dred[w * 256 + (r + 8) * 16 + cp]      = make_float2(d0[2], d0[3]);
    *(float2*)&dred[w * 256 + r * 16 + 8 + cp]        = make_float2(d1[0], d1[1]);
    *(float2*)&dred[w * 256 + (r + 8) * 16 + 8 + cp]  = make_float2(d1[2], d1[3]);
    __syncthreads();

    // reduce 8 warp partials; t -> (b = t>>4, o = t&15)
    float sum = 0.f;
#pragma unroll
    for (int ww = 0; ww < 8; ww++) sum += dred[ww * 256 + t];
    int b = t >> 4, o = t & 15;
    g_off[((size_t)b * CC + c) * DOUTT + o] = sum * (1.0f / (float)NN);
}

// ---------------------------------------------------------------------------
// kC (R6 exact, measured 32.6us)
// ---------------------------------------------------------------------------
__global__ __launch_bounds__(256, 3) void kC(const float* __restrict__ x,
                                             const int* __restrict__ pid,
                                             const float* __restrict__ b1,
                                             float* __restrict__ out) {
    int c = blockIdx.x, b = blockIdx.y;
    int t = threadIdx.x;
    int q = t & 3, g = t >> 2;

    const int* pc = pid + c * 256;
    int ns[4];
    ns[0] = __ldg(pc + g);
    ns[1] = __ldg(pc + g + 64);
    ns[2] = __ldg(pc + g + 128);
    ns[3] = __ldg(pc + g + 192);

    float4 wreg[4][4];
    float  bs[4];
    const float* wc = g_wdt + c * 256;
#pragma unroll
    for (int oo = 0; oo < 4; oo++) {
        int o = 4 * q + oo;
        bs[oo] = __ldg(&g_off[((size_t)b * CC + c) * DOUTT + o]) + __ldg(b1 + o);
#pragma unroll
        for (int p = 0; p < 4; p++)
            wreg[oo][p] = *(const float4*)(wc + o * 16 + 4 * (q ^ p));
    }

    const float* xb = x + (size_t)b * NN * DINN;
    float* ob = out + (size_t)b * NN * DOUTT;

#pragma unroll
    for (int j = 0; j < 4; j++) {
        int n = ns[j];
        float4 X0 = ((const float4*)(xb + (size_t)n * DINN))[q];
        float4 X1 = shfl_xor_f4(X0, 1);
        float4 X2 = shfl_xor_f4(X0, 2);
        float4 X3 = shfl_xor_f4(X0, 3);

        float r0 = bs[0], r1 = bs[1], r2 = bs[2], r3 = bs[3];
        r0 += dot4(wreg[0][0], X0) + dot4(wreg[0][1], X1) + dot4(wreg[0][2], X2) + dot4(wreg[0][3], X3);
        r1 += dot4(wreg[1][0], X0) + dot4(wreg[1][1], X1) + dot4(wreg[1][2], X2) + dot4(wreg[1][3], X3);
        r2 += dot4(wreg[2][0], X0) + dot4(wreg[2][1], X1) + dot4(wreg[2][2], X2) + dot4(wreg[2][3], X3);
        r3 += dot4(wreg[3][0], X0) + dot4(wreg[3][1], X1) + dot4(wreg[3][2], X2) + dot4(wreg[3][3], X3);

        ((float4*)(ob + (size_t)n * DOUTT))[q] = make_float4(r0, r1, r2, r3);
    }
}

extern "C" void kernel_launch(void* const* d_in, const int* in_sizes, int n_in,
                              void* d_out, int out_size) {
    const float* x     = (const float*)d_in[0];
    const float* wdiag = (const float*)d_in[1];
    const float* woff  = (const float*)d_in[2];
    const float* b1    = (const float*)d_in[3];
    const int*   pid   = (const int*)d_in[4];
    float* out = (float*)d_out;

    kT<<<256, 256>>>(wdiag);
    kA<<<dim3(CC, BB), 256>>>(x, pid);
    kB<<<CC, 256>>>(woff);
    kC<<<dim3(CC, BB), 256>>>(x, pid, b1, out);
}